// round 15
// baseline (speedup 1.0000x reference)
#include <cuda_runtime.h>
#include <cuda_fp16.h>
#include <cstdint>

#define BATCH 2048
#define MF    26
#define KE    32
#define C1    (MF*MF)
#define NPAIR 351
#define NTRI  3276
#define NJ    3328
#define OUTW  256
#define NKS   8

typedef unsigned long long ull;

__device__ int    g_e2pqj[NTRI];
__device__ float  g_W1s[384 * 128];       // [pq][i]; row 351 = b1, 352.. = 0
__device__ float  g_W2t[NJ * 128];        // [i][j*128+h], i-row stride NJ
__device__ float  g_U[352 * NJ];          // [pq][j*128+h]; row 351 = v
__device__ __half g_W1h[128 * 384];       // W1s^T hi [i][pq]
__device__ __half g_W1l[128 * 384];
__device__ __half g_TFh[BATCH * 384];     // G-vector hi [b][e]
__device__ __half g_TFl[BATCH * 384];
__device__ __half g_Th[BATCH * NJ];       // T hi [b][e]
__device__ __half g_Tl[BATCH * NJ];
__device__ __half g_Uh[128 * NJ];         // Up^T hi [h][e]
__device__ __half g_Ul[128 * NJ];
__device__ float  g_P[NKS * BATCH * 128];

// feat task table: seg | jlo<<8 | jhi<<16 | emitG<<24 ; -1 = none
#define TK(s, lo, hi, g) ((s) | ((lo) << 8) | ((hi) << 16) | ((g) << 24))
__constant__ int c_tasks[12][2] = {
    { TK(0,  0,  9, 1), -1 },
    { TK(0,  9, 18, 0), -1 },
    { TK(0, 18, 26, 0), TK(10, 24, 26, 1) },
    { TK(1,  7, 17, 1), -1 },
    { TK(1, 17, 26, 0), -1 },
    { TK(2, 10, 20, 1), -1 },
    { TK(2, 20, 26, 0), TK(9, 23, 26, 1) },
    { TK(3, 13, 23, 1), -1 },
    { TK(3, 23, 26, 0), TK(6, 19, 26, 1) },
    { TK(4, 15, 26, 1), -1 },
    { TK(5, 17, 26, 1), -1 },
    { TK(7, 20, 26, 1), TK(8, 22, 26, 1) },
};

#define FMA2(a, x, y) asm("fma.rn.f32x2 %0, %1, %2, %0;" : "+l"(a) : "l"(x), "l"(y))
#define MUL2(d, x, y) asm("mul.rn.f32x2 %0, %1, %2;" : "=l"(d) : "l"(x), "l"(y))
#define ADD2(a, x)    asm("add.rn.f32x2 %0, %0, %1;" : "+l"(a) : "l"(x))
#define DUP2(d, f)    asm("mov.b64 %0, {%1, %1};" : "=l"(d) : "f"(f))

__device__ __forceinline__ unsigned sptr(const void* p) {
    return (unsigned)__cvta_generic_to_shared(p);
}
__device__ __forceinline__ void cp16(unsigned s, const void* g) {
    asm volatile("cp.async.cg.shared.global [%0], [%1], 16;\n" :: "r"(s), "l"(g));
}
#define CP_COMMIT() asm volatile("cp.async.commit_group;\n" ::)
#define CP_WAIT0()  asm volatile("cp.async.wait_group 0;\n" ::)
#define CP_WAIT1()  asm volatile("cp.async.wait_group 1;\n" ::)

#define LDSM4(r0, r1, r2, r3, addr) \
    asm volatile("ldmatrix.sync.aligned.m8n8.x4.shared.b16 {%0,%1,%2,%3}, [%4];" \
        : "=r"(r0), "=r"(r1), "=r"(r2), "=r"(r3) : "r"(addr))
#define MMA16816(d, a, b) \
    asm volatile("mma.sync.aligned.m16n8k16.row.col.f32.f16.f16.f32 " \
        "{%0,%1,%2,%3}, {%4,%5,%6,%7}, {%8,%9}, {%0,%1,%2,%3};" \
        : "+f"((d)[0]), "+f"((d)[1]), "+f"((d)[2]), "+f"((d)[3]) \
        : "r"((a)[0]), "r"((a)[1]), "r"((a)[2]), "r"((a)[3]), "r"((b)[0]), "r"((b)[1]))

__device__ __forceinline__ int pq_off(int p) { return p * MF - (p * (p - 1)) / 2; }

__device__ __forceinline__ void pq_decode(int pq, int& p, int& q) {
    p = (int)(26.5f - sqrtf(702.25f - 2.0f * (float)pq));
    if (p < 0) p = 0;
    while (p > 0 && pq_off(p) > pq) p--;
    while (pq_off(p + 1) <= pq) p++;
    q = p + (pq - pq_off(p));
}

__device__ __forceinline__ float hadd2(ull a) {
    float2 f = *reinterpret_cast<float2*>(&a);
    return f.x + f.y;
}

// ---------------------------------------------------------------------------
// kA_prep: [0,416) W2 transpose; [416,608) W1s (+fp16 transposed); [608,621) e2pqj
// ---------------------------------------------------------------------------
__global__ __launch_bounds__(256) void kA_prep(
    const float* __restrict__ W1, const float* __restrict__ b1,
    const float* __restrict__ W2)
{
    const int bx = blockIdx.x;
    const int t  = threadIdx.x;
    if (bx < 416) {
        __shared__ float tile[32][33];
        int c0 = (bx % 104) * 32;
        int h0 = (bx / 104) * 32;
        int tx = t & 31, ty = t >> 5;
#pragma unroll
        for (int r = 0; r < 4; r++)
            tile[ty + 8 * r][tx] = W2[(size_t)(h0 + ty + 8 * r) * NJ + c0 + tx];
        __syncthreads();
#pragma unroll
        for (int r = 0; r < 4; r++)
            g_W2t[(size_t)(c0 + ty + 8 * r) * 128 + h0 + tx] = tile[tx][ty + 8 * r];
    } else if (bx < 608) {
        int idx = (bx - 416) * 256 + t;
        int pq = idx >> 7, i = idx & 127;
        float v = 0.f;
        if (pq == NPAIR) v = b1[i];
        else if (pq < NPAIR) {
            int p, q; pq_decode(pq, p, q);
            v = W1[i * C1 + p * MF + q];
            if (p < q) v += W1[i * C1 + q * MF + p];
        }
        g_W1s[idx] = v;
        __half hi = __float2half_rn(v);
        g_W1h[(size_t)i * 384 + pq] = hi;
        g_W1l[(size_t)i * 384 + pq] = __float2half_rn(v - __half2float(hi));
    } else {
        int e = (bx - 608) * 256 + t;
        if (e < NTRI) {
            int rem = e, p = 0;
            while (rem >= (MF - p) * (MF - p + 1) / 2) { rem -= (MF - p) * (MF - p + 1) / 2; p++; }
            int q = p;
            while (rem >= MF - q) { rem -= MF - q; q++; }
            g_e2pqj[e] = p | (q << 8) | ((q + rem) << 16);
        }
    }
}

// ---------------------------------------------------------------------------
// k_feat: 1 batch/block, 384 thr, 2 CTAs/SM. Task-balanced q-major segments
//   (~10 j-units per warp), vectorized half2 epilogue.
// ---------------------------------------------------------------------------
__global__ __launch_bounds__(384, 2) void k_feat(const float* __restrict__ x0g) {
    __shared__ ull   xsr[MF][18];
    __shared__ float sF[3712];   // G 0..350 | T 352..3627 | sx 3628..3653
    const int b = blockIdx.x;
    const int t = threadIdx.x;

    for (int idx = t; idx < MF * 16; idx += 384) {
        int j = idx >> 4, kp = idx & 15;
        xsr[j][kp] = *reinterpret_cast<const ull*>(
            x0g + (size_t)b * (MF * KE) + j * KE + 2 * kp);
    }
    __syncthreads();

    if (t < MF) {   // sx
        ull s0 = 0, s1 = 0;
#pragma unroll
        for (int cc = 0; cc < 8; cc++) {
            ulonglong2 v = *reinterpret_cast<const ulonglong2*>(&xsr[t][2 * cc]);
            ADD2(s0, v.x); ADD2(s1, v.y);
        }
        ADD2(s0, s1);
        sF[3628 + t] = hadd2(s0);
    }

    const int w = t >> 5, lane = t & 31;

#pragma unroll
    for (int ti = 0; ti < 2; ti++) {
        const int task = c_tasks[w][ti];
        if (task < 0) continue;
        const int seg = task & 255;
        const int jlo = (task >> 8) & 255;
        const int jhi = (task >> 16) & 255;
        const int doG = (task >> 24) & 1;

        int eq = seg * 32 + lane;
        const bool v = eq < NPAIR;
        if (!v) eq = 0;
        int q = 0;
        while ((q + 1) * (q + 2) / 2 <= eq) q++;
        int p = eq - q * (q + 1) / 2;
        int rb = 0;
        for (int pp = 0; pp < p; pp++) rb += (MF - pp) * (MF - pp + 1) / 2;
        for (int qq = p; qq < q; qq++) rb += MF - qq;

        ull xx[16];
#pragma unroll
        for (int cc = 0; cc < 8; cc++) {
            ulonglong2 xp = *reinterpret_cast<const ulonglong2*>(&xsr[p][2 * cc]);
            ulonglong2 xq = *reinterpret_cast<const ulonglong2*>(&xsr[q][2 * cc]);
            MUL2(xx[2 * cc],     xp.x, xq.x);
            MUL2(xx[2 * cc + 1], xp.y, xq.y);
        }

        if (doG) {
            ull g0 = 0, g1 = 0;
#pragma unroll
            for (int kp = 0; kp < 16; kp += 2) { ADD2(g0, xx[kp]); ADD2(g1, xx[kp + 1]); }
            ADD2(g0, g1);
            if (v) sF[pq_off(p) + q - p] = hadd2(g0);
        }

        float* sTrow = sF + 352 + rb - q;
        for (int j = jlo; j < jhi; j++) {
            ull a0 = 0, a1 = 0, a2 = 0, a3 = 0;
#pragma unroll
            for (int cc = 0; cc < 8; cc++) {
                ulonglong2 xj = *reinterpret_cast<const ulonglong2*>(&xsr[j][2 * cc]);
                if (cc & 1) { FMA2(a2, xx[2 * cc], xj.x); FMA2(a3, xx[2 * cc + 1], xj.y); }
                else        { FMA2(a0, xx[2 * cc], xj.x); FMA2(a1, xx[2 * cc + 1], xj.y); }
            }
            ADD2(a0, a1); ADD2(a2, a3); ADD2(a0, a2);
            if (v && j >= q) sTrow[j] = hadd2(a0);
        }
    }
    __syncthreads();

    // G-vector fp16 hi/lo [b][384], half2 stores (192 pairs)
    if (t < 192) {
        int e = 2 * t;
        float v0 = (e < NPAIR) ? sF[e] : (e == NPAIR ? 32.0f : 0.0f);
        float v1 = (e + 1 < NPAIR) ? sF[e + 1] : (e + 1 == NPAIR ? 32.0f : 0.0f);
        __half h0 = __float2half_rn(v0), h1 = __float2half_rn(v1);
        size_t o = (size_t)b * 384 + e;
        *reinterpret_cast<__half2*>(&g_TFh[o]) = __halves2half2(h0, h1);
        *reinterpret_cast<__half2*>(&g_TFl[o]) = __halves2half2(
            __float2half_rn(v0 - __half2float(h0)),
            __float2half_rn(v1 - __half2float(h1)));
    }

    // T-vector fp16 hi/lo [b][3328], half2 stores (1664 pairs)
    for (int e2 = t; e2 < NJ / 2; e2 += 384) {
        int e = 2 * e2;
        float v0, v1;
        {
            int ee = e;
            if (ee < NTRI)            v0 = sF[352 + ee];
            else if (ee < NTRI + MF)  v0 = sF[3628 + (ee - NTRI)];
            else if (ee == NTRI + MF) v0 = 32.0f;
            else                      v0 = 0.0f;
            ee = e + 1;
            if (ee < NTRI)            v1 = sF[352 + ee];
            else if (ee < NTRI + MF)  v1 = sF[3628 + (ee - NTRI)];
            else if (ee == NTRI + MF) v1 = 32.0f;
            else                      v1 = 0.0f;
        }
        __half h0 = __float2half_rn(v0), h1 = __float2half_rn(v1);
        size_t o = (size_t)b * NJ + e;
        *reinterpret_cast<__half2*>(&g_Th[o]) = __halves2half2(h0, h1);
        *reinterpret_cast<__half2*>(&g_Tl[o]) = __halves2half2(
            __float2half_rn(v0 - __half2float(h0)),
            __float2half_rn(v1 - __half2float(h1)));
    }
}

// ---------------------------------------------------------------------------
// k_u: U = W1s @ W2t. 48m x 128n tiles, grid 208, 384 thr.
// ---------------------------------------------------------------------------
__global__ __launch_bounds__(384) void k_u() {
    __shared__ float As[32][52];
    __shared__ float Bs[32][132];
    const int t = threadIdx.x;
    int m0 = (blockIdx.x & 7) * 48;
    int n0 = (blockIdx.x >> 3) * 128;
    const int tx = t & 31, ty = t >> 5;

    ull acc[4][2];
#pragma unroll
    for (int r = 0; r < 4; r++) { acc[r][0] = 0ULL; acc[r][1] = 0ULL; }

    for (int kc = 0; kc < 128; kc += 32) {
        __syncthreads();
        {
            int row = t >> 3, c4 = t & 7;
            float4 v = *reinterpret_cast<const float4*>(
                g_W1s + (size_t)(m0 + row) * 128 + kc + 4 * c4);
            As[4 * c4 + 0][row] = v.x;
            As[4 * c4 + 1][row] = v.y;
            As[4 * c4 + 2][row] = v.z;
            As[4 * c4 + 3][row] = v.w;
        }
#pragma unroll
        for (int l = 0; l < 3; l++) {
            int idx = t + 384 * l;
            if (idx < 1024) {
                int row = idx >> 5, c4 = idx & 31;
                *reinterpret_cast<float4*>(&Bs[row][4 * c4]) =
                    *reinterpret_cast<const float4*>(g_W2t + (size_t)(kc + row) * NJ + n0 + 4 * c4);
            }
        }
        __syncthreads();

#pragma unroll
        for (int kk = 0; kk < 32; kk++) {
            float4 a = *reinterpret_cast<const float4*>(&As[kk][4 * ty]);
            ulonglong2 wv = *reinterpret_cast<const ulonglong2*>(&Bs[kk][4 * tx]);
            ull d;
            DUP2(d, a.x); FMA2(acc[0][0], wv.x, d); FMA2(acc[0][1], wv.y, d);
            DUP2(d, a.y); FMA2(acc[1][0], wv.x, d); FMA2(acc[1][1], wv.y, d);
            DUP2(d, a.z); FMA2(acc[2][0], wv.x, d); FMA2(acc[2][1], wv.y, d);
            DUP2(d, a.w); FMA2(acc[3][0], wv.x, d); FMA2(acc[3][1], wv.y, d);
        }
    }
#pragma unroll
    for (int r = 0; r < 4; r++) {
        int m = m0 + 4 * ty + r;
        if (m < 352) {
            float* dst = g_U + (size_t)m * NJ + n0 + 4 * tx;
            *reinterpret_cast<float2*>(dst)     = *reinterpret_cast<float2*>(&acc[r][0]);
            *reinterpret_cast<float2*>(dst + 2) = *reinterpret_cast<float2*>(&acc[r][1]);
        }
    }
}

// ---------------------------------------------------------------------------
// k_fold: grid (52,4) — 64e x 32h tiles, warp-uniform e reads, smem
//   transpose, e-coalesced fp16 writes.
// ---------------------------------------------------------------------------
__global__ __launch_bounds__(256) void k_fold(const float* __restrict__ b2) {
    __shared__ float tile[64][33];
    const int t  = threadIdx.x;
    const int e0 = blockIdx.x * 64;
    const int h0 = blockIdx.y * 32;
    const int hl = t & 31;
    const int h  = h0 + hl;
    const int er = t >> 5;

#pragma unroll
    for (int i = 0; i < 8; i++) {
        int el = er + 8 * i;
        int e = e0 + el;
        float val = 0.f;
        if (e < NTRI) {
            int c = g_e2pqj[e];
            int p = c & 255, q = (c >> 8) & 255, j = (c >> 16) & 255;
            #define CU(PQ, J) g_U[(size_t)(PQ) * NJ + (J) * 128 + h]
            if (p < q) {
                if (q < j) val = CU(pq_off(p) + q - p, j) + CU(pq_off(p) + j - p, q) + CU(pq_off(q) + j - q, p);
                else       val = CU(pq_off(p) + q - p, q) + CU(pq_off(q), p);
            } else {
                if (q < j) val = CU(pq_off(p), j) + CU(pq_off(p) + j - p, p);
                else       val = CU(pq_off(p), p);
            }
            #undef CU
        } else if (e < NTRI + MF) {
            val = g_U[(size_t)NPAIR * NJ + (e - NTRI) * 128 + h];
        } else if (e == NTRI + MF) {
            val = b2[h];
        }
        tile[el][hl] = val;
    }
    __syncthreads();

#pragma unroll
    for (int i = 0; i < 8; i++) {
        int idx = t + 256 * i;
        int h2 = idx >> 6;
        int el = idx & 63;
        float val = tile[el][h2];
        __half hi = __float2half_rn(val);
        float lo = val - __half2float(hi);
        size_t o = (size_t)(h0 + h2) * NJ + e0 + el;
        g_Uh[o] = hi;
        g_Ul[o] = __float2half_rn(lo);
    }
}

// ---------------------------------------------------------------------------
// k_tc: grid 288 (single wave at 2 CTAs/SM), all HMMA, dyn smem 96K.
// ---------------------------------------------------------------------------
#define STAGE_BYTES 49152
__global__ __launch_bounds__(256) void k_tc(float* __restrict__ out) {
    extern __shared__ __align__(16) char dyn[];
    const int t = threadIdx.x;
    const int id = blockIdx.x;
    const int wid = t >> 5, lane = t & 31;
    const int wm = wid >> 2, wn = wid & 3;
    const int mr0 = 32 * wm, nr0 = 32 * wn;

    const __half *Ah, *Al, *Bh, *Bl;
    int astr, bstr, nch, kbase, b0;
    float* dst;
    int dstr;
    if (id < 256) {
        int bt = id >> 3, ks = id & 7;
        b0 = bt * 64;
        Ah = g_Th; Al = g_Tl; Bh = g_Uh; Bl = g_Ul;
        astr = NJ; bstr = NJ;
        nch = (ks < 4) ? 7 : 6;
        kbase = 64 * ((ks < 4) ? 7 * ks : 28 + 6 * (ks - 4));
        dst = g_P + (size_t)ks * BATCH * 128;
        dstr = 128;
    } else {
        b0 = (id - 256) * 64;
        Ah = g_TFh; Al = g_TFl; Bh = g_W1h; Bl = g_W1l;
        astr = 384; bstr = 384;
        nch = 6; kbase = 0;
        dst = out;
        dstr = OUTW;
    }

    const uint32_t sBase = sptr(dyn);

    float d[2][4][4];
#pragma unroll
    for (int mf = 0; mf < 2; mf++)
#pragma unroll
        for (int nf = 0; nf < 4; nf++)
#pragma unroll
            for (int e = 0; e < 4; e++) d[mf][nf][e] = 0.f;

    const int aR = t >> 3, aC = t & 7;
    const uint32_t aSw0 = (uint32_t)(aR * 128 + ((aC ^ (aR & 7)) << 4));
    const int aR1 = (t + 256) >> 3;
    const uint32_t aSw1 = (uint32_t)(aR1 * 128 + ((aC ^ (aR1 & 7)) << 4));

    const int aRowOff = lane & 15;
    const uint32_t aColX = (uint32_t)((lane >> 4) << 4);
    const int bRow4 = (lane & 7) + ((lane >> 4) << 3);
    const uint32_t bCol4 = (uint32_t)(((lane >> 3) & 1) << 4);

    auto stage_issue = [&](int ch) {
        const int kc = kbase + ch * 64;
        const uint32_t sb = sBase + (uint32_t)(ch & 1) * STAGE_BYTES;
        {
            size_t go0 = (size_t)(b0 + aR) * astr + kc + aC * 8;
            size_t go1 = (size_t)(b0 + aR1) * astr + kc + aC * 8;
            cp16(sb + aSw0,        Ah + go0);
            cp16(sb + 8192 + aSw0, Al + go0);
            cp16(sb + aSw1,        Ah + go1);
            cp16(sb + 8192 + aSw1, Al + go1);
        }
#pragma unroll
        for (int i = 0; i < 4; i++) {
            int u = t + 256 * i;
            int r = u >> 3, c8 = u & 7;
            uint32_t sw = (uint32_t)(r * 128 + ((c8 ^ (r & 7)) << 4));
            size_t go = (size_t)r * bstr + kc + c8 * 8;
            cp16(sb + 16384 + sw, Bh + go);
            cp16(sb + 32768 + sw, Bl + go);
        }
        CP_COMMIT();
    };

    stage_issue(0);
    if (nch > 1) stage_issue(1);

    for (int ch = 0; ch < nch; ch++) {
        if (ch + 1 < nch) { CP_WAIT1(); } else { CP_WAIT0(); }
        __syncthreads();

        const uint32_t sb = sBase + (uint32_t)(ch & 1) * STAGE_BYTES;
        const uint32_t sA = sb, sB = sb + 16384;

#pragma unroll
        for (int k16 = 0; k16 < 4; k16++) {
            uint32_t ah[2][4], al[2][4], bhf[4][2], blf[4][2];
#pragma unroll
            for (int mf = 0; mf < 2; mf++) {
                int row = mr0 + 16 * mf + aRowOff;
                uint32_t colb = (uint32_t)(k16 * 32) + aColX;
                uint32_t addr = sA + (uint32_t)(row * 128) + (colb ^ ((uint32_t)(row & 7) << 4));
                LDSM4(ah[mf][0], ah[mf][1], ah[mf][2], ah[mf][3], addr);
                LDSM4(al[mf][0], al[mf][1], al[mf][2], al[mf][3], addr + 8192);
            }
#pragma unroll
            for (int p2 = 0; p2 < 2; p2++) {
                int row = nr0 + 16 * p2 + bRow4;
                uint32_t colb = (uint32_t)(k16 * 32) + bCol4;
                uint32_t addr = sB + (uint32_t)(row * 128) + (colb ^ ((uint32_t)(row & 7) << 4));
                LDSM4(bhf[2 * p2][0], bhf[2 * p2][1], bhf[2 * p2 + 1][0], bhf[2 * p2 + 1][1], addr);
                LDSM4(blf[2 * p2][0], blf[2 * p2][1], blf[2 * p2 + 1][0], blf[2 * p2 + 1][1], addr + 16384);
            }
#pragma unroll
            for (int mf = 0; mf < 2; mf++)
#pragma unroll
                for (int nf = 0; nf < 4; nf++) {
                    MMA16816(d[mf][nf], ah[mf], bhf[nf]);
                    MMA16816(d[mf][nf], ah[mf], blf[nf]);
                    MMA16816(d[mf][nf], al[mf], bhf[nf]);
                }
        }

        __syncthreads();
        if (ch + 2 < nch) stage_issue(ch + 2);
    }

    const int g = lane >> 2, tq = lane & 3;
#pragma unroll
    for (int mf = 0; mf < 2; mf++) {
        int rbase = b0 + mr0 + 16 * mf;
#pragma unroll
        for (int nf = 0; nf < 4; nf++) {
            int h = nr0 + 8 * nf + 2 * tq;
            *reinterpret_cast<float2*>(dst + (size_t)(rbase + g) * dstr + h) =
                make_float2(d[mf][nf][0], d[mf][nf][1]);
            *reinterpret_cast<float2*>(dst + (size_t)(rbase + g + 8) * dstr + h) =
                make_float2(d[mf][nf][2], d[mf][nf][3]);
        }
    }
}

// ---------------------------------------------------------------------------
// k_red: out[:,128:256] = sum of 8 partials
// ---------------------------------------------------------------------------
__global__ void k_red(float* __restrict__ out) {
    int gid = blockIdx.x * blockDim.x + threadIdx.x;
    int b = gid >> 7, h = gid & 127;
    const int N = BATCH * 128;
    float s0 = g_P[gid]         + g_P[gid + N];
    float s1 = g_P[gid + 2 * N] + g_P[gid + 3 * N];
    float s2 = g_P[gid + 4 * N] + g_P[gid + 5 * N];
    float s3 = g_P[gid + 6 * N] + g_P[gid + 7 * N];
    out[(size_t)b * OUTW + 128 + h] = (s0 + s1) + (s2 + s3);
}

// ---------------------------------------------------------------------------
// launch: two-stream graph (weight chain hidden under feat).
// ---------------------------------------------------------------------------
extern "C" void kernel_launch(void* const* d_in, const int* in_sizes, int n_in,
                              void* d_out, int out_size) {
    const float* inputs = (const float*)d_in[0];
    const float* W1     = (const float*)d_in[1];
    const float* b1     = (const float*)d_in[2];
    const float* W2     = (const float*)d_in[3];
    const float* b2     = (const float*)d_in[4];
    float* out = (float*)d_out;

    cudaFuncSetAttribute(k_tc, cudaFuncAttributeMaxDynamicSharedMemorySize, 2 * STAGE_BYTES);

    cudaStream_t s2;
    cudaStreamCreateWithFlags(&s2, cudaStreamNonBlocking);
    cudaEvent_t evFork, evJoin;
    cudaEventCreateWithFlags(&evFork, cudaEventDisableTiming);
    cudaEventCreateWithFlags(&evJoin, cudaEventDisableTiming);

    cudaEventRecord(evFork, 0);
    cudaStreamWaitEvent(s2, evFork, 0);

    kA_prep<<<621, 256, 0, s2>>>(W1, b1, W2);
    k_u<<<208, 384, 0, s2>>>();
    k_fold<<<dim3(52, 4), 256, 0, s2>>>(b2);
    cudaEventRecord(evJoin, s2);

    k_feat<<<BATCH, 384>>>(inputs);

    cudaStreamWaitEvent(0, evJoin, 0);
    k_tc<<<288, 256, 2 * STAGE_BYTES>>>(out);
    k_red<<<(BATCH * 128) / 256, 256>>>(out);

    cudaEventDestroy(evFork);
    cudaEventDestroy(evJoin);
    cudaStreamDestroy(s2);
}